// round 9
// baseline (speedup 1.0000x reference)
#include <cuda_runtime.h>
#include <cuda_bf16.h>

// OrdinalRegressionLoss: mean over B x 4 of
//   max(x,0) - x*[j < target] + log1p(exp(-|x|))
// B = 8,388,608 rows, logits fp32 (B,4), targets int32 (B,).
// 160 MiB streamed once -> HBM-bound.
// R8 warp-dense layout (best measured) + reduced math:
//   sum_j log1p(e^-|xj|) = log( prod_j (1+e^-|xj|) )   -> 5 MUFU/row not 8
//   sum_{j<t} xj = prefix[t]                           -> 3 FADD + selects
// Fused threadfence-reduction tail (single launch).

#define NBLOCKS 740           // 148 SMs * 5 blocks, one wave
#define NTHREADS 256
#define ROWS_PER_WARP 128     // 4 rows per lane, lane-strided

__device__ float g_partials[NBLOCKS];
__device__ unsigned int g_count = 0;   // reset by last block -> graph-replay safe

__device__ __forceinline__ float row_loss(float4 l, int t) {
    // softplus-sum via product: log(prod(1+e^-|x|))
    float e0 = __expf(-fabsf(l.x));
    float e1 = __expf(-fabsf(l.y));
    float e2 = __expf(-fabsf(l.z));
    float e3 = __expf(-fabsf(l.w));
    float p01 = (1.0f + e0) * (1.0f + e1);
    float p23 = (1.0f + e2) * (1.0f + e3);
    float sp = __logf(p01 * p23);          // in [0, ~2.8], abs err ~1e-7

    float pos = fmaxf(l.x, 0.0f) + fmaxf(l.y, 0.0f)
              + fmaxf(l.z, 0.0f) + fmaxf(l.w, 0.0f);

    // prefix sums: xy = sum_{j < t} x_j, t in 0..4
    float s1 = l.x;
    float s2 = s1 + l.y;
    float s3 = s2 + l.z;
    float s4 = s3 + l.w;
    float xy = (t >= 4) ? s4 : (t == 3) ? s3 : (t == 2) ? s2 : (t == 1) ? s1 : 0.0f;

    return pos - xy + sp;
}

__device__ __forceinline__ float block_reduce(float acc, float* ws) {
    #pragma unroll
    for (int o = 16; o > 0; o >>= 1)
        acc += __shfl_down_sync(0xffffffffu, acc, o);
    int lane = threadIdx.x & 31;
    int wid  = threadIdx.x >> 5;
    if (lane == 0) ws[wid] = acc;
    __syncthreads();
    float v = 0.0f;
    if (wid == 0) {
        v = (lane < NTHREADS / 32) ? ws[lane] : 0.0f;
        #pragma unroll
        for (int o = 4; o > 0; o >>= 1)
            v += __shfl_down_sync(0xffffffffu, v, o);
    }
    return v;   // valid at (wid==0, lane==0)
}

__global__ void __launch_bounds__(NTHREADS, 5)
ordinal_loss_fused(const float4* __restrict__ logits4,
                   const int* __restrict__ targets,
                   int nrows, float inv_total, float* __restrict__ out) {
    __shared__ float ws[NTHREADS / 32];
    __shared__ bool is_last;

    int lane = threadIdx.x & 31;
    int gwarp = (blockIdx.x * blockDim.x + threadIdx.x) >> 5;
    int nwarps = (gridDim.x * blockDim.x) >> 5;
    int nchunks = nrows / ROWS_PER_WARP;

    float acc0 = 0.0f, acc1 = 0.0f;
    for (int c = gwarp; c < nchunks; c += nwarps) {
        int base = c * ROWS_PER_WARP;
        // 8 independent, perfectly coalesced streaming loads; streams 512B apart.
        float4 l0 = __ldcs(logits4 + base + lane);
        float4 l1 = __ldcs(logits4 + base + 32 + lane);
        float4 l2 = __ldcs(logits4 + base + 64 + lane);
        float4 l3 = __ldcs(logits4 + base + 96 + lane);
        int t0 = __ldcs(targets + base + lane);
        int t1 = __ldcs(targets + base + 32 + lane);
        int t2 = __ldcs(targets + base + 64 + lane);
        int t3 = __ldcs(targets + base + 96 + lane);
        acc0 += row_loss(l0, t0);
        acc1 += row_loss(l1, t1);
        acc0 += row_loss(l2, t2);
        acc1 += row_loss(l3, t3);
    }
    // tail rows (nrows % 128) — B is divisible; guard for safety.
    int rem_base = nchunks * ROWS_PER_WARP;
    int stride = gridDim.x * blockDim.x;
    for (int r = rem_base + blockIdx.x * blockDim.x + threadIdx.x; r < nrows; r += stride)
        acc0 += row_loss(__ldcs(logits4 + r), __ldcs(targets + r));

    float bsum = block_reduce(acc0 + acc1, ws);
    if (threadIdx.x == 0) {
        g_partials[blockIdx.x] = bsum;
        __threadfence();
        unsigned int old = atomicAdd(&g_count, 1u);
        is_last = (old == gridDim.x - 1);
    }
    __syncthreads();

    if (is_last) {
        float a = 0.0f;
        for (int j = threadIdx.x; j < (int)gridDim.x; j += NTHREADS)
            a += g_partials[j];
        __syncthreads();          // ws reuse hazard
        float total = block_reduce(a, ws);
        if (threadIdx.x == 0) {
            out[0] = total * inv_total;
            g_count = 0;          // reset for next graph replay
        }
    }
}

extern "C" void kernel_launch(void* const* d_in, const int* in_sizes, int n_in,
                              void* d_out, int out_size) {
    const float4* logits4 = (const float4*)d_in[0];   // (B,4) fp32
    const int* targets    = (const int*)d_in[1];      // (B,) int32 on device
    float* out = (float*)d_out;

    int nrows = in_sizes[1];                          // B
    float inv_total = 1.0f / ((float)nrows * 4.0f);

    ordinal_loss_fused<<<NBLOCKS, NTHREADS>>>(logits4, targets, nrows, inv_total, out);
}

// round 10
// speedup vs baseline: 1.0738x; 1.0738x over previous
#include <cuda_runtime.h>
#include <cuda_bf16.h>

// OrdinalRegressionLoss: mean over B x 4 of
//   max(x,0) - x*[j < target] + log1p(exp(-|x|))
// B = 8,388,608 rows, logits fp32 (B,4), targets int32 (B,).
// 160 MiB streamed once -> HBM-bound.
// R8 warp-dense layout (measured best: warp owns 128 consecutive rows,
// lane-strided x4; every LDG coalesced, streams 512B apart), with .cg
// cache policy (no L1 allocation for stream-once data).
// Fused threadfence-reduction tail (single launch).

#define NBLOCKS 740           // 148 SMs * 5 blocks, one wave
#define NTHREADS 256
#define ROWS_PER_WARP 128     // 4 rows per lane, lane-strided

__device__ float g_partials[NBLOCKS];
__device__ unsigned int g_count = 0;   // reset by last block -> graph-replay safe

__device__ __forceinline__ float bce_term(float x, float y) {
    float ax = fabsf(x);
    float sp = __logf(1.0f + __expf(-ax));   // log1p(exp(-ax)), ax>=0
    return fmaxf(x, 0.0f) - x * y + sp;
}

__device__ __forceinline__ float row_loss(float4 l, int t) {
    // 4 independent short chains -> max ILP (R9 lesson: don't serialize these)
    float s = bce_term(l.x, (float)(0 < t));
    s += bce_term(l.y, (float)(1 < t));
    s += bce_term(l.z, (float)(2 < t));
    s += bce_term(l.w, (float)(3 < t));
    return s;
}

__device__ __forceinline__ float block_reduce(float acc, float* ws) {
    #pragma unroll
    for (int o = 16; o > 0; o >>= 1)
        acc += __shfl_down_sync(0xffffffffu, acc, o);
    int lane = threadIdx.x & 31;
    int wid  = threadIdx.x >> 5;
    if (lane == 0) ws[wid] = acc;
    __syncthreads();
    float v = 0.0f;
    if (wid == 0) {
        v = (lane < NTHREADS / 32) ? ws[lane] : 0.0f;
        #pragma unroll
        for (int o = 4; o > 0; o >>= 1)
            v += __shfl_down_sync(0xffffffffu, v, o);
    }
    return v;   // valid at (wid==0, lane==0)
}

__global__ void __launch_bounds__(NTHREADS, 5)
ordinal_loss_fused(const float4* __restrict__ logits4,
                   const int* __restrict__ targets,
                   int nrows, float inv_total, float* __restrict__ out) {
    __shared__ float ws[NTHREADS / 32];
    __shared__ bool is_last;

    int lane = threadIdx.x & 31;
    int gwarp = (blockIdx.x * blockDim.x + threadIdx.x) >> 5;
    int nwarps = (gridDim.x * blockDim.x) >> 5;
    int nchunks = nrows / ROWS_PER_WARP;

    float acc = 0.0f;
    for (int c = gwarp; c < nchunks; c += nwarps) {
        int base = c * ROWS_PER_WARP;
        // 8 independent, perfectly coalesced loads; 4 streams 512B apart.
        float4 l0 = __ldcg(logits4 + base + lane);
        float4 l1 = __ldcg(logits4 + base + 32 + lane);
        float4 l2 = __ldcg(logits4 + base + 64 + lane);
        float4 l3 = __ldcg(logits4 + base + 96 + lane);
        int t0 = __ldcg(targets + base + lane);
        int t1 = __ldcg(targets + base + 32 + lane);
        int t2 = __ldcg(targets + base + 64 + lane);
        int t3 = __ldcg(targets + base + 96 + lane);
        acc += row_loss(l0, t0);
        acc += row_loss(l1, t1);
        acc += row_loss(l2, t2);
        acc += row_loss(l3, t3);
    }
    // tail rows (nrows % 128) — B is divisible; guard for safety.
    int rem_base = nchunks * ROWS_PER_WARP;
    int stride = gridDim.x * blockDim.x;
    for (int r = rem_base + blockIdx.x * blockDim.x + threadIdx.x; r < nrows; r += stride)
        acc += row_loss(__ldcg(logits4 + r), __ldcg(targets + r));

    float bsum = block_reduce(acc, ws);
    if (threadIdx.x == 0) {
        g_partials[blockIdx.x] = bsum;
        __threadfence();
        unsigned int old = atomicAdd(&g_count, 1u);
        is_last = (old == gridDim.x - 1);
    }
    __syncthreads();

    if (is_last) {
        float a = 0.0f;
        for (int j = threadIdx.x; j < (int)gridDim.x; j += NTHREADS)
            a += g_partials[j];
        __syncthreads();          // ws reuse hazard
        float total = block_reduce(a, ws);
        if (threadIdx.x == 0) {
            out[0] = total * inv_total;
            g_count = 0;          // reset for next graph replay
        }
    }
}

extern "C" void kernel_launch(void* const* d_in, const int* in_sizes, int n_in,
                              void* d_out, int out_size) {
    const float4* logits4 = (const float4*)d_in[0];   // (B,4) fp32
    const int* targets    = (const int*)d_in[1];      // (B,) int32 on device
    float* out = (float*)d_out;

    int nrows = in_sizes[1];                          // B
    float inv_total = 1.0f / ((float)nrows * 4.0f);

    ordinal_loss_fused<<<NBLOCKS, NTHREADS>>>(logits4, targets, nrows, inv_total, out);
}